// round 7
// baseline (speedup 1.0000x reference)
#include <cuda_runtime.h>
#include <cuda_bf16.h>
#include <cstdint>

// ---------------------------------------------------------------------------
// MultilayerDeformableC3D — mma.sync TF32 (3xTF32 split) implicit-im2col GEMM.
// R7: hi/lo split precomputed at STS (float2 smem), BM=64 for 2 CTAs/SM.
// ---------------------------------------------------------------------------

#define T_   8
#define H_   24
#define W_   24
#define N_   4608
#define CIN_ 256
#define KV_  27
#define KD_  6912

#define BM 64
#define BN 64
#define BK 16
#define NC (KD_ / BK)   // 432

// scratch
__device__ float g_col[(size_t)KD_ * N_];
__device__ float g_h1[(size_t)CIN_ * N_];
__device__ float g_h2[(size_t)CIN_ * N_];
__device__ float g_off[(size_t)81 * N_];
__device__ float g_xT[(size_t)N_ * CIN_];

__device__ __forceinline__ uint32_t tf32r(float v) {
    uint32_t r;
    asm("cvt.rna.tf32.f32 %0, %1;" : "=r"(r) : "f"(v));
    return r;
}
__device__ __forceinline__ float2 splitf(float v) {
    float hi = __uint_as_float(tf32r(v));
    return make_float2(hi, v - hi);
}
__device__ __forceinline__ void mma8(float c[4],
                                     uint32_t a0, uint32_t a1, uint32_t a2, uint32_t a3,
                                     uint32_t b0, uint32_t b1) {
    asm volatile(
        "mma.sync.aligned.m16n8k8.row.col.f32.tf32.tf32.f32 "
        "{%0,%1,%2,%3}, {%4,%5,%6,%7}, {%8,%9}, {%0,%1,%2,%3};"
        : "+f"(c[0]), "+f"(c[1]), "+f"(c[2]), "+f"(c[3])
        : "r"(a0), "r"(a1), "r"(a2), "r"(a3), "r"(b0), "r"(b1));
}

// ---------------------------------------------------------------------------
// GEMM: C[Mtot][N_] = A[Mtot][KD_] * B[KD_][N_] + bias (optional ReLU)
// FUSED: B rows gathered implicitly (im2col) from feature map [CIN_][N_]
// 128 thr = 4 warps (2m x 2n), warp tile 32x32. smem holds (hi,lo) float2.
// ---------------------------------------------------------------------------
template <bool RELU, bool FUSED>
__global__ void __launch_bounds__(128)
gemm_mma(const float* __restrict__ A, const float* __restrict__ Bsrc,
         const float* __restrict__ bias, float* __restrict__ C, int Mtot)
{
    __shared__ float2 As[2][BM][20];   // [m][k] (hi,lo); 16 used + pad
    __shared__ float2 Bs[2][BK][66];   // [k][n] (hi,lo); 64 used + pad
    __shared__ int    tbl[KV_];

    const int tid  = threadIdx.x;
    const int wid  = tid >> 5;
    const int lane = tid & 31;
    const int q = lane >> 2;          // 0..7
    const int r = lane & 3;           // 0..3
    const int m0 = blockIdx.y * BM;
    const int n0 = blockIdx.x * BN;
    const int m0w = (wid & 1) * 32;   // warp m offset
    const int n0w = (wid >> 1) * 32;  // warp n offset

    if (tid < KV_) {
        int dt = tid / 9 - 1, dh = (tid / 3) % 3 - 1, dw = tid % 3 - 1;
        tbl[tid] = dt * (H_ * W_) + dh * W_ + dw;
    }

    // ---- A (weights) load map: rows arow, arow+32; k-quad akq
    const int arow = tid >> 2;        // 0..31
    const int akq  = tid & 3;         // float4 index within 16-k row
    const bool av0 = (m0 + arow)      < Mtot;
    const bool av1 = (m0 + arow + 32) < Mtot;
    const float* ap0 = A + (size_t)(m0 + arow) * KD_ + akq * 4;
    const float* ap1 = A + (size_t)(m0 + arow + 32) * KD_ + akq * 4;

    // ---- B load map: column bn, 8 k-rows (rg*8..rg*8+7)
    const int bn = tid & 63;
    const int rg = tid >> 6;          // 0..1
    const int n  = n0 + bn;
    uint32_t vmask = 0;
    int ci8[8], k278[8];
    if (FUSED) {
        int nt_ = n / (H_ * W_);
        int rem = n - nt_ * (H_ * W_);
        int nh_ = rem / W_;
        int nw_ = rem - nh_ * W_;
        for (int k = 0; k < KV_; k++) {
            int dt = k / 9 - 1, dh = (k / 3) % 3 - 1, dw = k % 3 - 1;
            int tt = nt_ + dt, hh = nh_ + dh, ww = nw_ + dw;
            if ((unsigned)tt < (unsigned)T_ && (unsigned)hh < (unsigned)H_ &&
                (unsigned)ww < (unsigned)W_)
                vmask |= 1u << k;
        }
#pragma unroll
        for (int j = 0; j < 8; j++) {
            int kd0 = rg * 8 + j;          // 0..15 < 27
            ci8[j]  = 0;
            k278[j] = kd0;
        }
    }
    __syncthreads();   // tbl visible before first fused gather

    float4 ra0, ra1;
    float  rb[8];

    auto ldgA = [&](int k0) {
        const float4 z = {0.f, 0.f, 0.f, 0.f};
        ra0 = av0 ? __ldg((const float4*)(ap0 + k0)) : z;
        ra1 = av1 ? __ldg((const float4*)(ap1 + k0)) : z;
    };
    auto ldgB = [&](int k0) {
        if (FUSED) {
#pragma unroll
            for (int j = 0; j < 8; j++) {
                int k27 = k278[j], ci = ci8[j];
                float v = 0.f;
                if ((vmask >> k27) & 1u)
                    v = __ldg(Bsrc + (size_t)ci * N_ + n + tbl[k27]);
                rb[j] = v;
                k27 += BK;                     // advance by one chunk
                if (k27 >= KV_) { k27 -= KV_; ci++; }
                k278[j] = k27; ci8[j] = ci;
            }
        } else {
#pragma unroll
            for (int j = 0; j < 8; j++)
                rb[j] = __ldg(Bsrc + (size_t)(k0 + rg * 8 + j) * N_ + n);
        }
    };
    auto sts = [&](int p) {
#pragma unroll
        for (int j = 0; j < 4; j++) {
            As[p][arow][akq * 4 + j]      = splitf((&ra0.x)[j]);
            As[p][arow + 32][akq * 4 + j] = splitf((&ra1.x)[j]);
        }
#pragma unroll
        for (int j = 0; j < 8; j++)
            Bs[p][rg * 8 + j][bn] = splitf(rb[j]);
    };

    float acc[2][4][4];
#pragma unroll
    for (int mt = 0; mt < 2; mt++)
#pragma unroll
        for (int nt = 0; nt < 4; nt++)
#pragma unroll
            for (int j = 0; j < 4; j++) acc[mt][nt][j] = 0.f;

    // prologue
    ldgA(0); ldgB(0);
    sts(0);
    __syncthreads();

    for (int c = 0; c < NC; c++) {
        const int p = c & 1;
        if (c + 1 < NC) { ldgA((c + 1) * BK); ldgB((c + 1) * BK); }

#pragma unroll
        for (int ks = 0; ks < 2; ks++) {
            const int kb = ks * 8;
            // A fragments: (hi,lo) pairs via LDS.64
            float2 a[2][4];
#pragma unroll
            for (int mt = 0; mt < 2; mt++) {
                a[mt][0] = As[p][m0w + mt * 16 + q][kb + r];
                a[mt][1] = As[p][m0w + mt * 16 + q + 8][kb + r];
                a[mt][2] = As[p][m0w + mt * 16 + q][kb + r + 4];
                a[mt][3] = As[p][m0w + mt * 16 + q + 8][kb + r + 4];
            }
            // B fragments
            float2 b[4][2];
#pragma unroll
            for (int nt = 0; nt < 4; nt++) {
                b[nt][0] = Bs[p][kb + r][n0w + nt * 8 + q];
                b[nt][1] = Bs[p][kb + r + 4][n0w + nt * 8 + q];
            }
            // 3xTF32: hi*hi + hi*lo + lo*hi
#pragma unroll
            for (int mt = 0; mt < 2; mt++)
#pragma unroll
                for (int nt = 0; nt < 4; nt++) {
                    uint32_t ah0 = __float_as_uint(a[mt][0].x);
                    uint32_t ah1 = __float_as_uint(a[mt][1].x);
                    uint32_t ah2 = __float_as_uint(a[mt][2].x);
                    uint32_t ah3 = __float_as_uint(a[mt][3].x);
                    uint32_t al0 = __float_as_uint(a[mt][0].y);
                    uint32_t al1 = __float_as_uint(a[mt][1].y);
                    uint32_t al2 = __float_as_uint(a[mt][2].y);
                    uint32_t al3 = __float_as_uint(a[mt][3].y);
                    uint32_t bh0 = __float_as_uint(b[nt][0].x);
                    uint32_t bh1 = __float_as_uint(b[nt][1].x);
                    uint32_t bl0 = __float_as_uint(b[nt][0].y);
                    uint32_t bl1 = __float_as_uint(b[nt][1].y);
                    mma8(acc[mt][nt], ah0, ah1, ah2, ah3, bh0, bh1);
                    mma8(acc[mt][nt], ah0, ah1, ah2, ah3, bl0, bl1);
                    mma8(acc[mt][nt], al0, al1, al2, al3, bh0, bh1);
                }
        }

        if (c + 1 < NC) sts((c + 1) & 1);
        __syncthreads();
    }

    // ---- epilogue: bias(+ReLU), float2 stores
#pragma unroll
    for (int mt = 0; mt < 2; mt++) {
        int row0 = m0 + m0w + mt * 16 + q;
        int row1 = row0 + 8;
        float bv0 = (row0 < Mtot) ? __ldg(bias + row0) : 0.f;
        float bv1 = (row1 < Mtot) ? __ldg(bias + row1) : 0.f;
#pragma unroll
        for (int nt = 0; nt < 4; nt++) {
            int cn = n0 + n0w + nt * 8 + 2 * r;
            float2 o0, o1;
            o0.x = acc[mt][nt][0] + bv0;
            o0.y = acc[mt][nt][1] + bv0;
            o1.x = acc[mt][nt][2] + bv1;
            o1.y = acc[mt][nt][3] + bv1;
            if (RELU) {
                o0.x = fmaxf(o0.x, 0.f); o0.y = fmaxf(o0.y, 0.f);
                o1.x = fmaxf(o1.x, 0.f); o1.y = fmaxf(o1.y, 0.f);
            }
            if (row0 < Mtot) *(float2*)&C[(size_t)row0 * N_ + cn] = o0;
            if (row1 < Mtot) *(float2*)&C[(size_t)row1 * N_ + cn] = o1;
        }
    }
}

// ---------------------------------------------------------------------------
// transpose: xT[n][ci] = x[ci][n]
// ---------------------------------------------------------------------------
__global__ void transpose_k(const float* __restrict__ x, float* __restrict__ xT)
{
    __shared__ float tl[32][33];
    int nb = blockIdx.x * 32, cb = blockIdx.y * 32;
    for (int j = threadIdx.y; j < 32; j += 8)
        tl[j][threadIdx.x] = x[(size_t)(cb + j) * N_ + nb + threadIdx.x];
    __syncthreads();
    for (int j = threadIdx.y; j < 32; j += 8)
        xT[(size_t)(nb + j) * CIN_ + cb + threadIdx.x] = tl[threadIdx.x][j];
}

// ---------------------------------------------------------------------------
// deform_col: col[(ci*27+k)][n] via trilinear interp; xT is [n][ci] so the
// 8 corner gathers are float4 loads along ci.
// ---------------------------------------------------------------------------
__global__ void deform_col_k(const float* __restrict__ xT,
                             const float* __restrict__ off,
                             float* __restrict__ col)
{
    int n = blockIdx.x * blockDim.x + threadIdx.x;
    if (n >= N_) return;
    int k = blockIdx.y;

    int t = n / (H_ * W_);
    int hw = n - t * (H_ * W_);
    int h = hw / W_;
    int w = hw - h * W_;

    int dt = k / 9 - 1, dh = (k / 3) % 3 - 1, dw = k % 3 - 1;

    float pt = (float)(t + dt) + off[(size_t)(k * 3 + 0) * N_ + n];
    float ph = (float)(h + dh) + off[(size_t)(k * 3 + 1) * N_ + n];
    float pw = (float)(w + dw) + off[(size_t)(k * 3 + 2) * N_ + n];

    float ft = floorf(pt), fh = floorf(ph), fw = floorf(pw);
    float at = pt - ft, ah = ph - fh, aw = pw - fw;
    int it = (int)ft, ih = (int)fh, iw = (int)fw;

    size_t idx8[8];
    float  wt8[8];
#pragma unroll
    for (int c = 0; c < 8; c++) {
        int ddt = (c >> 2) & 1, ddh = (c >> 1) & 1, ddw = c & 1;
        int tt = it + ddt, hh = ih + ddh, ww = iw + ddw;
        bool valid = (tt >= 0 && tt < T_ && hh >= 0 && hh < H_ && ww >= 0 && ww < W_);
        int tc = min(max(tt, 0), T_ - 1);
        int hc = min(max(hh, 0), H_ - 1);
        int wc = min(max(ww, 0), W_ - 1);
        float wg = (ddt ? at : 1.f - at) * (ddh ? ah : 1.f - ah) * (ddw ? aw : 1.f - aw);
        wt8[c]  = valid ? wg : 0.f;
        idx8[c] = (size_t)((tc * H_ + hc) * W_ + wc) * CIN_;
    }

    const size_t stride = (size_t)KV_ * N_;
    for (int c0 = 0; c0 < CIN_; c0 += 4) {
        float4 a4 = make_float4(0.f, 0.f, 0.f, 0.f);
#pragma unroll
        for (int c = 0; c < 8; c++) {
            float4 g = __ldg((const float4*)(xT + idx8[c] + c0));
            a4.x += wt8[c] * g.x;
            a4.y += wt8[c] * g.y;
            a4.z += wt8[c] * g.z;
            a4.w += wt8[c] * g.w;
        }
        size_t b = ((size_t)c0 * KV_ + k) * N_ + n;
        col[b]              = a4.x;
        col[b + stride]     = a4.y;
        col[b + 2 * stride] = a4.z;
        col[b + 3 * stride] = a4.w;
    }
}

// ---------------------------------------------------------------------------
extern "C" void kernel_launch(void* const* d_in, const int* in_sizes, int n_in,
                              void* d_out, int out_size)
{
    const float* x     = (const float*)d_in[0];
    const float* l1_w  = (const float*)d_in[1];
    const float* l1_b  = (const float*)d_in[2];
    const float* l2_w  = (const float*)d_in[3];
    const float* l2_b  = (const float*)d_in[4];
    const float* l3_w  = (const float*)d_in[5];
    const float* l3_b  = (const float*)d_in[6];
    const float* def_w = (const float*)d_in[7];
    const float* def_b = (const float*)d_in[8];
    const float* c3d_w = (const float*)d_in[9];
    const float* c3d_b = (const float*)d_in[10];
    float* out = (float*)d_out;

    float *col, *h1, *h2, *off, *xT;
    cudaGetSymbolAddress((void**)&col, g_col);
    cudaGetSymbolAddress((void**)&h1,  g_h1);
    cudaGetSymbolAddress((void**)&h2,  g_h2);
    cudaGetSymbolAddress((void**)&off, g_off);
    cudaGetSymbolAddress((void**)&xT,  g_xT);

    dim3 g256(N_ / BN, 256 / BM);             // (72, 4) = 288 CTAs
    dim3 g81 (N_ / BN, (81 + BM - 1) / BM);   // (72, 2) = 144 CTAs

    gemm_mma<true,  true ><<<g256, 128>>>(l1_w, x,  l1_b, h1, 256);
    gemm_mma<true,  true ><<<g256, 128>>>(l2_w, h1, l2_b, h2, 256);
    gemm_mma<true,  true ><<<g256, 128>>>(l3_w, h2, l3_b, h1, 256);
    gemm_mma<false, true ><<<g81,  128>>>(def_w, h1, def_b, off, 81);

    transpose_k<<<dim3(N_ / 32, CIN_ / 32), dim3(32, 8)>>>(x, xT);
    deform_col_k<<<dim3(N_ / 128, KV_), 128>>>(xT, off, col);

    gemm_mma<false, false><<<g256, 128>>>(c3d_w, col, c3d_b, out, 256);
}

// round 8
// speedup vs baseline: 1.3416x; 1.3416x over previous
#include <cuda_runtime.h>
#include <cuda_bf16.h>
#include <cstdint>

// ---------------------------------------------------------------------------
// MultilayerDeformableC3D — mma.sync TF32 (3xTF32 split) implicit-im2col GEMM.
// R8: BM=128/BN=64/256thr + split-at-STS (float2 smem) + split-K partials
//     (+ combine kernel) for 2 CTAs/SM and shorter serial K-chains.
// ---------------------------------------------------------------------------

#define T_   8
#define H_   24
#define W_   24
#define N_   4608
#define CIN_ 256
#define KV_  27
#define KD_  6912

#define BM 128
#define BN 64
#define BK 16

// dynamic smem layout (float2 elements)
// As: [2][BM][20]  (16 used k + pad)   -> 2*128*20 = 5120 f2 = 40960 B x2 buf? no:
//   As buffer already includes both stages in dim0.
#define AS_STRIDE 20
#define BS_STRIDE 66
#define AS_F2     (2 * BM * AS_STRIDE)           // 5120 float2
#define BS_F2     (2 * BK * BS_STRIDE)           // 2112 float2
#define SMEM_BYTES ((AS_F2 + BS_F2) * 8 + 128)   // ~58KB? (5120+2112)*8=57856 +128

// scratch
__device__ float g_col[(size_t)KD_ * N_];
__device__ float g_h1[(size_t)CIN_ * N_];
__device__ float g_h2[(size_t)CIN_ * N_];
__device__ float g_off[(size_t)81 * N_];
__device__ float g_xT[(size_t)N_ * CIN_];
__device__ float g_part[(size_t)4 * 256 * N_];   // split-K partials (max S=4, M<=256)

__device__ __forceinline__ uint32_t tf32r(float v) {
    uint32_t r;
    asm("cvt.rna.tf32.f32 %0, %1;" : "=r"(r) : "f"(v));
    return r;
}
__device__ __forceinline__ float2 splitf(float v) {
    float hi = __uint_as_float(tf32r(v));
    return make_float2(hi, v - hi);
}
__device__ __forceinline__ void mma8(float c[4],
                                     uint32_t a0, uint32_t a1, uint32_t a2, uint32_t a3,
                                     uint32_t b0, uint32_t b1) {
    asm volatile(
        "mma.sync.aligned.m16n8k8.row.col.f32.tf32.tf32.f32 "
        "{%0,%1,%2,%3}, {%4,%5,%6,%7}, {%8,%9}, {%0,%1,%2,%3};"
        : "+f"(c[0]), "+f"(c[1]), "+f"(c[2]), "+f"(c[3])
        : "r"(a0), "r"(a1), "r"(a2), "r"(a3), "r"(b0), "r"(b1));
}

// ---------------------------------------------------------------------------
// Split-K GEMM partial: part[z][Mtot][N_] = A[.][kseg] * B[kseg][.]
// FUSED: B rows gathered implicitly (im2col) from feature map [CIN_][N_].
// 256 thr = 8 warps (4m x 2n), warp tile 32x32. smem holds (hi,lo) float2.
// gridDim.z = S (K segments).
// ---------------------------------------------------------------------------
template <bool FUSED>
__global__ void __launch_bounds__(256)
gemm_part(const float* __restrict__ A, const float* __restrict__ Bsrc,
          float* __restrict__ part, int Mtot)
{
    extern __shared__ float2 sm[];
    float2* As = sm;             // [2][BM][AS_STRIDE]
    float2* Bs = sm + AS_F2;     // [2][BK][BS_STRIDE]
    __shared__ int tbl[KV_];

    const int tid  = threadIdx.x;
    const int wid  = tid >> 5;
    const int lane = tid & 31;
    const int q = lane >> 2;          // 0..7
    const int r = lane & 3;           // 0..3
    const int m0 = blockIdx.y * BM;
    const int n0 = blockIdx.x * BN;
    const int m0w = (wid & 3) * 32;
    const int n0w = (wid >> 2) * 32;

    const int S    = gridDim.z;
    const int kbeg = blockIdx.z * (KD_ / S);
    const int NCl  = KD_ / (BK * S);

    if (tid < KV_) {
        int dt = tid / 9 - 1, dh = (tid / 3) % 3 - 1, dw = tid % 3 - 1;
        tbl[tid] = dt * (H_ * W_) + dh * W_ + dw;
    }

    // ---- A load map: rows arow, arow+64; k-quad akq
    const int arow = tid >> 2;        // 0..63
    const int akq  = tid & 3;
    const bool av0 = (m0 + arow)      < Mtot;
    const bool av1 = (m0 + arow + 64) < Mtot;
    const float* ap0 = A + (size_t)(m0 + arow) * KD_ + kbeg + akq * 4;
    const float* ap1 = A + (size_t)(m0 + arow + 64) * KD_ + kbeg + akq * 4;

    // ---- B load map: column bn, 4 k-rows rg*4..rg*4+3
    const int bn = tid & 63;
    const int rg = tid >> 6;          // 0..3
    const int n  = n0 + bn;
    uint32_t vmask = 0;
    int ci4[4], k274[4];
    if (FUSED) {
        int nt_ = n / (H_ * W_);
        int rem = n - nt_ * (H_ * W_);
        int nh_ = rem / W_;
        int nw_ = rem - nh_ * W_;
        for (int k = 0; k < KV_; k++) {
            int dt = k / 9 - 1, dh = (k / 3) % 3 - 1, dw = k % 3 - 1;
            int tt = nt_ + dt, hh = nh_ + dh, ww = nw_ + dw;
            if ((unsigned)tt < (unsigned)T_ && (unsigned)hh < (unsigned)H_ &&
                (unsigned)ww < (unsigned)W_)
                vmask |= 1u << k;
        }
#pragma unroll
        for (int j = 0; j < 4; j++) {
            int kd0 = kbeg + rg * 4 + j;
            int ci  = kd0 / KV_;
            ci4[j]  = ci;
            k274[j] = kd0 - ci * KV_;
        }
    }
    __syncthreads();   // tbl visible

    float4 ra0, ra1;
    float  rb[4];

    auto ldgA = [&](int koff) {
        const float4 z4 = {0.f, 0.f, 0.f, 0.f};
        ra0 = av0 ? __ldg((const float4*)(ap0 + koff)) : z4;
        ra1 = av1 ? __ldg((const float4*)(ap1 + koff)) : z4;
    };
    auto ldgB = [&](int koff) {
        if (FUSED) {
#pragma unroll
            for (int j = 0; j < 4; j++) {
                int k27 = k274[j], ci = ci4[j];
                float v = 0.f;
                if ((vmask >> k27) & 1u)
                    v = __ldg(Bsrc + (size_t)ci * N_ + n + tbl[k27]);
                rb[j] = v;
                k27 += BK;
                if (k27 >= KV_) { k27 -= KV_; ci++; }
                k274[j] = k27; ci4[j] = ci;
            }
        } else {
#pragma unroll
            for (int j = 0; j < 4; j++)
                rb[j] = __ldg(Bsrc + (size_t)(kbeg + koff + rg * 4 + j) * N_ + n);
        }
    };
    auto sts = [&](int p) {
        float2* Ad0 = As + ((size_t)p * BM + arow) * AS_STRIDE + akq * 4;
        float2* Ad1 = Ad0 + (size_t)64 * AS_STRIDE;
        // pack (hi,lo,hi,lo) pairs -> 2x 16B stores per row
#pragma unroll
        for (int j = 0; j < 4; j += 2) {
            float2 s0 = splitf((&ra0.x)[j]), s1 = splitf((&ra0.x)[j + 1]);
            *(float4*)(Ad0 + j) = make_float4(s0.x, s0.y, s1.x, s1.y);
            float2 t0 = splitf((&ra1.x)[j]), t1 = splitf((&ra1.x)[j + 1]);
            *(float4*)(Ad1 + j) = make_float4(t0.x, t0.y, t1.x, t1.y);
        }
#pragma unroll
        for (int j = 0; j < 4; j++)
            Bs[((size_t)p * BK + rg * 4 + j) * BS_STRIDE + bn] = splitf(rb[j]);
    };

    float acc[2][4][4];
#pragma unroll
    for (int mt = 0; mt < 2; mt++)
#pragma unroll
        for (int nt = 0; nt < 4; nt++)
#pragma unroll
            for (int j = 0; j < 4; j++) acc[mt][nt][j] = 0.f;

    ldgA(0); ldgB(0);
    sts(0);
    __syncthreads();

    for (int c = 0; c < NCl; c++) {
        const int p = c & 1;
        if (c + 1 < NCl) { ldgA((c + 1) * BK); ldgB((c + 1) * BK); }

#pragma unroll
        for (int ks = 0; ks < 2; ks++) {
            const int kb = ks * 8;
            float2 a[2][4];
#pragma unroll
            for (int mt = 0; mt < 2; mt++) {
                const float2* Ar0 = As + ((size_t)p * BM + m0w + mt * 16 + q) * AS_STRIDE + kb;
                const float2* Ar1 = Ar0 + (size_t)8 * AS_STRIDE;
                a[mt][0] = Ar0[r];
                a[mt][1] = Ar1[r];
                a[mt][2] = Ar0[r + 4];
                a[mt][3] = Ar1[r + 4];
            }
            float2 b[4][2];
#pragma unroll
            for (int nt = 0; nt < 4; nt++) {
                const float2* Br0 = Bs + ((size_t)p * BK + kb + r) * BS_STRIDE + n0w + nt * 8 + q;
                b[nt][0] = Br0[0];
                b[nt][1] = Br0[4 * BS_STRIDE];
            }
#pragma unroll
            for (int mt = 0; mt < 2; mt++) {
                uint32_t ah0 = __float_as_uint(a[mt][0].x);
                uint32_t ah1 = __float_as_uint(a[mt][1].x);
                uint32_t ah2 = __float_as_uint(a[mt][2].x);
                uint32_t ah3 = __float_as_uint(a[mt][3].x);
                uint32_t al0 = __float_as_uint(a[mt][0].y);
                uint32_t al1 = __float_as_uint(a[mt][1].y);
                uint32_t al2 = __float_as_uint(a[mt][2].y);
                uint32_t al3 = __float_as_uint(a[mt][3].y);
#pragma unroll
                for (int nt = 0; nt < 4; nt++) {
                    uint32_t bh0 = __float_as_uint(b[nt][0].x);
                    uint32_t bh1 = __float_as_uint(b[nt][1].x);
                    uint32_t bl0 = __float_as_uint(b[nt][0].y);
                    uint32_t bl1 = __float_as_uint(b[nt][1].y);
                    mma8(acc[mt][nt], ah0, ah1, ah2, ah3, bh0, bh1);
                    mma8(acc[mt][nt], ah0, ah1, ah2, ah3, bl0, bl1);
                    mma8(acc[mt][nt], al0, al1, al2, al3, bh0, bh1);
                }
            }
        }

        if (c + 1 < NCl) sts((c + 1) & 1);
        __syncthreads();
    }

    // ---- store raw partials (bias/relu in combine)
    float* P = part + (size_t)blockIdx.z * Mtot * N_;
#pragma unroll
    for (int mt = 0; mt < 2; mt++) {
        int row0 = m0 + m0w + mt * 16 + q;
        int row1 = row0 + 8;
#pragma unroll
        for (int nt = 0; nt < 4; nt++) {
            int cn = n0 + n0w + nt * 8 + 2 * r;
            if (row0 < Mtot)
                *(float2*)&P[(size_t)row0 * N_ + cn] =
                    make_float2(acc[mt][nt][0], acc[mt][nt][1]);
            if (row1 < Mtot)
                *(float2*)&P[(size_t)row1 * N_ + cn] =
                    make_float2(acc[mt][nt][2], acc[mt][nt][3]);
        }
    }
}

// ---------------------------------------------------------------------------
// combine: out[m][n] = (relu?) ( sum_s part[s][m][n] + bias[m] )
// float4 over M*N_ elements. Deterministic fixed-order sum.
// ---------------------------------------------------------------------------
template <bool RELU, int S>
__global__ void combine_k(const float* __restrict__ part,
                          const float* __restrict__ bias,
                          float* __restrict__ out, int Mtot)
{
    int idx = blockIdx.x * blockDim.x + threadIdx.x;      // float4 index
    int total = Mtot * N_ / 4;
    if (idx >= total) return;
    size_t i4 = (size_t)idx * 4;
    int m = (int)(i4 / N_);
    const size_t MN = (size_t)Mtot * N_;
    float4 s = __ldg((const float4*)(part + i4));
#pragma unroll
    for (int z = 1; z < S; z++) {
        float4 p = __ldg((const float4*)(part + z * MN + i4));
        s.x += p.x; s.y += p.y; s.z += p.z; s.w += p.w;
    }
    float bv = __ldg(bias + m);
    s.x += bv; s.y += bv; s.z += bv; s.w += bv;
    if (RELU) {
        s.x = fmaxf(s.x, 0.f); s.y = fmaxf(s.y, 0.f);
        s.z = fmaxf(s.z, 0.f); s.w = fmaxf(s.w, 0.f);
    }
    *(float4*)(out + i4) = s;
}

// ---------------------------------------------------------------------------
// transpose: xT[n][ci] = x[ci][n]
// ---------------------------------------------------------------------------
__global__ void transpose_k(const float* __restrict__ x, float* __restrict__ xT)
{
    __shared__ float tl[32][33];
    int nb = blockIdx.x * 32, cb = blockIdx.y * 32;
    for (int j = threadIdx.y; j < 32; j += 8)
        tl[j][threadIdx.x] = x[(size_t)(cb + j) * N_ + nb + threadIdx.x];
    __syncthreads();
    for (int j = threadIdx.y; j < 32; j += 8)
        xT[(size_t)(nb + j) * CIN_ + cb + threadIdx.x] = tl[threadIdx.x][j];
}

// ---------------------------------------------------------------------------
// deform_col: col[(ci*27+k)][n] via trilinear interp; xT is [n][ci] so the
// 8 corner gathers are float4 loads along ci.
// ---------------------------------------------------------------------------
__global__ void deform_col_k(const float* __restrict__ xT,
                             const float* __restrict__ off,
                             float* __restrict__ col)
{
    int n = blockIdx.x * blockDim.x + threadIdx.x;
    if (n >= N_) return;
    int k = blockIdx.y;

    int t = n / (H_ * W_);
    int hw = n - t * (H_ * W_);
    int h = hw / W_;
    int w = hw - h * W_;

    int dt = k / 9 - 1, dh = (k / 3) % 3 - 1, dw = k % 3 - 1;

    float pt = (float)(t + dt) + off[(size_t)(k * 3 + 0) * N_ + n];
    float ph = (float)(h + dh) + off[(size_t)(k * 3 + 1) * N_ + n];
    float pw = (float)(w + dw) + off[(size_t)(k * 3 + 2) * N_ + n];

    float ft = floorf(pt), fh = floorf(ph), fw = floorf(pw);
    float at = pt - ft, ah = ph - fh, aw = pw - fw;
    int it = (int)ft, ih = (int)fh, iw = (int)fw;

    size_t idx8[8];
    float  wt8[8];
#pragma unroll
    for (int c = 0; c < 8; c++) {
        int ddt = (c >> 2) & 1, ddh = (c >> 1) & 1, ddw = c & 1;
        int tt = it + ddt, hh = ih + ddh, ww = iw + ddw;
        bool valid = (tt >= 0 && tt < T_ && hh >= 0 && hh < H_ && ww >= 0 && ww < W_);
        int tc = min(max(tt, 0), T_ - 1);
        int hc = min(max(hh, 0), H_ - 1);
        int wc = min(max(ww, 0), W_ - 1);
        float wg = (ddt ? at : 1.f - at) * (ddh ? ah : 1.f - ah) * (ddw ? aw : 1.f - aw);
        wt8[c]  = valid ? wg : 0.f;
        idx8[c] = (size_t)((tc * H_ + hc) * W_ + wc) * CIN_;
    }

    const size_t stride = (size_t)KV_ * N_;
    for (int c0 = 0; c0 < CIN_; c0 += 4) {
        float4 a4 = make_float4(0.f, 0.f, 0.f, 0.f);
#pragma unroll
        for (int c = 0; c < 8; c++) {
            float4 g = __ldg((const float4*)(xT + idx8[c] + c0));
            a4.x += wt8[c] * g.x;
            a4.y += wt8[c] * g.y;
            a4.z += wt8[c] * g.z;
            a4.w += wt8[c] * g.w;
        }
        size_t b = ((size_t)c0 * KV_ + k) * N_ + n;
        col[b]              = a4.x;
        col[b + stride]     = a4.y;
        col[b + 2 * stride] = a4.z;
        col[b + 3 * stride] = a4.w;
    }
}

// ---------------------------------------------------------------------------
extern "C" void kernel_launch(void* const* d_in, const int* in_sizes, int n_in,
                              void* d_out, int out_size)
{
    const float* x     = (const float*)d_in[0];
    const float* l1_w  = (const float*)d_in[1];
    const float* l1_b  = (const float*)d_in[2];
    const float* l2_w  = (const float*)d_in[3];
    const float* l2_b  = (const float*)d_in[4];
    const float* l3_w  = (const float*)d_in[5];
    const float* l3_b  = (const float*)d_in[6];
    const float* def_w = (const float*)d_in[7];
    const float* def_b = (const float*)d_in[8];
    const float* c3d_w = (const float*)d_in[9];
    const float* c3d_b = (const float*)d_in[10];
    float* out = (float*)d_out;

    float *col, *h1, *h2, *off, *xT, *part;
    cudaGetSymbolAddress((void**)&col,  g_col);
    cudaGetSymbolAddress((void**)&h1,   g_h1);
    cudaGetSymbolAddress((void**)&h2,   g_h2);
    cudaGetSymbolAddress((void**)&off,  g_off);
    cudaGetSymbolAddress((void**)&xT,   g_xT);
    cudaGetSymbolAddress((void**)&part, g_part);

    cudaFuncSetAttribute(gemm_part<true>,  cudaFuncAttributeMaxDynamicSharedMemorySize, SMEM_BYTES);
    cudaFuncSetAttribute(gemm_part<false>, cudaFuncAttributeMaxDynamicSharedMemorySize, SMEM_BYTES);

    dim3 g256(N_ / BN, 256 / BM, 2);   // (72, 2, 2) = 288 CTAs
    dim3 g81 (N_ / BN, 1, 4);          // (72, 1, 4) = 288 CTAs

    const int cb256 = (256 * N_ / 4 + 255) / 256;
    const int cb81  = (81  * N_ / 4 + 255) / 256;

    gemm_part<true ><<<g256, 256, SMEM_BYTES>>>(l1_w, x,  part, 256);
    combine_k<true, 2><<<cb256, 256>>>(part, l1_b, h1, 256);
    gemm_part<true ><<<g256, 256, SMEM_BYTES>>>(l2_w, h1, part, 256);
    combine_k<true, 2><<<cb256, 256>>>(part, l2_b, h2, 256);
    gemm_part<true ><<<g256, 256, SMEM_BYTES>>>(l3_w, h2, part, 256);
    combine_k<true, 2><<<cb256, 256>>>(part, l3_b, h1, 256);
    gemm_part<true ><<<g81,  256, SMEM_BYTES>>>(def_w, h1, part, 81);
    combine_k<false, 4><<<cb81, 256>>>(part, def_b, off, 81);

    transpose_k<<<dim3(N_ / 32, CIN_ / 32), dim3(32, 8)>>>(x, xT);
    deform_col_k<<<dim3(N_ / 128, KV_), 128>>>(xT, off, col);

    gemm_part<false><<<g256, 256, SMEM_BYTES>>>(c3d_w, col, part, 256);
    combine_k<false, 2><<<cb256, 256>>>(part, c3d_b, out, 256);
}